// round 1
// baseline (speedup 1.0000x reference)
#include <cuda_runtime.h>

#define N_CELLS 10000
#define N_GENES 2000
#define DD      64

// Layout: 8 lanes cooperate on one edge (lane sub = lane&7 owns elements
// sub*8 .. sub*8+7 of the D=64 feature dim). One warp processes 4 edges per
// iteration. Reductions via 3 levels of shfl_xor within each 8-lane group.
__global__ __launch_bounds__(512) void zinb_edge_kernel(
    const float* __restrict__ c_feat,    // [N_CELLS, 64]
    const float* __restrict__ g_feat,    // [N_GENES, 64]
    const float* __restrict__ cs_factor, // [N_CELLS]
    const float* __restrict__ gs_factor, // [N_GENES]
    const int*   __restrict__ src,       // [E]
    const int*   __restrict__ dst,       // [E]
    const float* __restrict__ Wm, const float* __restrict__ bm,
    const float* __restrict__ Wd, const float* __restrict__ bd,
    const float* __restrict__ Wp, const float* __restrict__ bp,
    float* __restrict__ out,             // [3*E]: mu | disp | pi
    int E)
{
    __shared__ float s_cs[N_CELLS];
    __shared__ float s_gs[N_GENES];
    for (int i = threadIdx.x; i < N_CELLS; i += blockDim.x) s_cs[i] = cs_factor[i];
    for (int i = threadIdx.x; i < N_GENES; i += blockDim.x) s_gs[i] = gs_factor[i];
    __syncthreads();

    const int lane = threadIdx.x & 31;
    const int grp  = lane >> 3;   // which of the warp's 4 edges
    const int sub  = lane & 7;    // position within the 8-lane group

    // Per-thread slice of the three weight vectors: elements sub*8 .. sub*8+7
    const float4* Wm4 = reinterpret_cast<const float4*>(Wm) + (sub << 1);
    const float4* Wd4 = reinterpret_cast<const float4*>(Wd) + (sub << 1);
    const float4* Wp4 = reinterpret_cast<const float4*>(Wp) + (sub << 1);
    const float4 wma = __ldg(Wm4), wmb = __ldg(Wm4 + 1);
    const float4 wda = __ldg(Wd4), wdb = __ldg(Wd4 + 1);
    const float4 wpa = __ldg(Wp4), wpb = __ldg(Wp4 + 1);
    const float bmv = __ldg(bm), bdv = __ldg(bd), bpv = __ldg(bp);

    float* __restrict__ out_mu   = out;
    float* __restrict__ out_disp = out + E;
    float* __restrict__ out_pi   = out + 2 * (long long)E;

    const float4* c4 = reinterpret_cast<const float4*>(c_feat);
    const float4* g4 = reinterpret_cast<const float4*>(g_feat);

    const int nQuads = (E + 3) >> 2;
    const int warpId = (blockIdx.x * blockDim.x + threadIdx.x) >> 5;
    const int nWarps = (gridDim.x * blockDim.x) >> 5;

    for (int q = warpId; q < nQuads; q += nWarps) {
        const int e     = q * 4 + grp;
        const bool valid = (e < E);
        int s = 0, d = 0;
        if (valid) { s = __ldg(src + e); d = __ldg(dst + e); }

        // 256B row reads: each 8-lane group covers a full 64-float row.
        const float4* cp = c4 + ((long long)s << 4) + (sub << 1);
        const float4* gp = g4 + ((long long)d << 4) + (sub << 1);
        // c_feat: bypass L1 (stream through L2), keep L1 for g_feat reuse.
        const float4 ca = __ldcg(cp), cb = __ldcg(cp + 1);
        const float4 ga = __ldg(gp),  gb = __ldg(gp + 1);

        float4 ha, hb;
        ha.x = ca.x * ga.x; ha.y = ca.y * ga.y; ha.z = ca.z * ga.z; ha.w = ca.w * ga.w;
        hb.x = cb.x * gb.x; hb.y = cb.y * gb.y; hb.z = cb.z * gb.z; hb.w = cb.w * gb.w;

        float sm = ha.x * wma.x;
        sm = fmaf(ha.y, wma.y, sm); sm = fmaf(ha.z, wma.z, sm); sm = fmaf(ha.w, wma.w, sm);
        sm = fmaf(hb.x, wmb.x, sm); sm = fmaf(hb.y, wmb.y, sm);
        sm = fmaf(hb.z, wmb.z, sm); sm = fmaf(hb.w, wmb.w, sm);

        float sd = ha.x * wda.x;
        sd = fmaf(ha.y, wda.y, sd); sd = fmaf(ha.z, wda.z, sd); sd = fmaf(ha.w, wda.w, sd);
        sd = fmaf(hb.x, wdb.x, sd); sd = fmaf(hb.y, wdb.y, sd);
        sd = fmaf(hb.z, wdb.z, sd); sd = fmaf(hb.w, wdb.w, sd);

        float sp = ha.x * wpa.x;
        sp = fmaf(ha.y, wpa.y, sp); sp = fmaf(ha.z, wpa.z, sp); sp = fmaf(ha.w, wpa.w, sp);
        sp = fmaf(hb.x, wpb.x, sp); sp = fmaf(hb.y, wpb.y, sp);
        sp = fmaf(hb.z, wpb.z, sp); sp = fmaf(hb.w, wpb.w, sp);

        // Reduce within each 8-lane group (xor offsets stay inside the group).
        #pragma unroll
        for (int off = 4; off > 0; off >>= 1) {
            sm += __shfl_xor_sync(0xffffffffu, sm, off);
            sd += __shfl_xor_sync(0xffffffffu, sd, off);
            sp += __shfl_xor_sync(0xffffffffu, sp, off);
        }

        if (sub == 0 && valid) {
            const float gsv = s_gs[d];
            const float csv = s_cs[s];

            // mu_ = sigmoid(h.Wm + bm), pi = sigmoid(h.Wp + bp)
            const float mu_ = 1.0f / (1.0f + expf(-(sm + bmv)));
            const float piv = 1.0f / (1.0f + expf(-(sp + bpv)));
            const float disp_ = sd + bdv;

            // disp = clip(softplus(gs * disp_), 1e-4, 1e4)  (stable softplus, jax form)
            const float x  = gsv * disp_;
            const float spv = fmaxf(x, 0.0f) + log1pf(expf(-fabsf(x)));
            const float dispv = fminf(fmaxf(spv, 1e-4f), 1e4f);

            // mu = cs * clip(exp(gs * mu_) - 1, 1e-5, 1e6)
            const float muv = csv * fminf(fmaxf(expf(gsv * mu_) - 1.0f, 1e-5f), 1e6f);

            out_mu[e]   = muv;
            out_disp[e] = dispv;
            out_pi[e]   = piv;
        }
    }
}

extern "C" void kernel_launch(void* const* d_in, const int* in_sizes, int n_in,
                              void* d_out, int out_size) {
    const float* c_feat    = (const float*)d_in[0];
    const float* g_feat    = (const float*)d_in[1];
    const float* cs_factor = (const float*)d_in[2];
    const float* gs_factor = (const float*)d_in[3];
    const int*   src       = (const int*)d_in[4];
    const int*   dst       = (const int*)d_in[5];
    const float* Wm        = (const float*)d_in[6];
    const float* bm        = (const float*)d_in[7];
    const float* Wd        = (const float*)d_in[8];
    const float* bd        = (const float*)d_in[9];
    const float* Wp        = (const float*)d_in[10];
    const float* bp        = (const float*)d_in[11];
    float* out = (float*)d_out;

    const int E = in_sizes[4];

    // Persistent-ish grid: amortize the 48KB smem fill of cs/gs per block.
    const int threads = 512;
    const int blocks  = 592;  // 4 * 148 SMs; grid-stride covers all edges
    zinb_edge_kernel<<<blocks, threads>>>(
        c_feat, g_feat, cs_factor, gs_factor, src, dst,
        Wm, bm, Wd, bd, Wp, bp, out, E);
}

// round 5
// speedup vs baseline: 1.3684x; 1.3684x over previous
#include <cuda_runtime.h>
#include <cuda_bf16.h>
#include <cstdint>

#define N_CELLS 10000
#define N_GENES 2000
#define DD      64
#define TILE    128
#define MT      79                  // ceil(10000/128)
#define NTT     47                  // 6016/128
#define M_PAD   (MT * TILE)         // 10112
#define N_COLS  (3 * N_GENES)       // 6000  (n = gene*3 + head)
#define N_PAD   (NTT * TILE)        // 6016
#define SA      144                 // smem row stride bytes (72 bf16, conflict-free)

// ---------------- device scratch (static; no runtime allocation) ------------
__device__ __nv_bfloat16 g_Ahi[M_PAD * DD];
__device__ __nv_bfloat16 g_Alo[M_PAD * DD];
__device__ __nv_bfloat16 g_Bhi[N_PAD * DD];
__device__ __nv_bfloat16 g_Blo[N_PAD * DD];
__device__ float g_C[(size_t)M_PAD * N_PAD];     // 243 MB, row-major [M_PAD][6016]

// ---------------- helpers ----------------------------------------------------
__device__ __forceinline__ uint32_t smem_u32(const void* p) {
    uint32_t a;
    asm("{ .reg .u64 t; cvta.to.shared.u64 t, %1; cvt.u32.u64 %0, t; }" : "=r"(a) : "l"(p));
    return a;
}

__device__ __forceinline__ void ldm4(uint32_t* r, uint32_t addr) {
    asm volatile("ldmatrix.sync.aligned.m8n8.x4.shared.b16 {%0,%1,%2,%3}, [%4];"
                 : "=r"(r[0]), "=r"(r[1]), "=r"(r[2]), "=r"(r[3]) : "r"(addr));
}

__device__ __forceinline__ void mma16816(float* c, const uint32_t* a,
                                         uint32_t b0, uint32_t b1) {
    asm volatile(
        "mma.sync.aligned.m16n8k16.row.col.f32.bf16.bf16.f32 "
        "{%0,%1,%2,%3}, {%4,%5,%6,%7}, {%8,%9}, {%0,%1,%2,%3};"
        : "+f"(c[0]), "+f"(c[1]), "+f"(c[2]), "+f"(c[3])
        : "r"(a[0]), "r"(a[1]), "r"(a[2]), "r"(a[3]), "r"(b0), "r"(b1));
}

// ---------------- phase 0: split inputs into bf16 hi/lo (fused) --------------
// Covers both A (M_PAD*64 elems) and B (N_PAD*64 elems) in one launch.
__global__ void prep_AB(const float* __restrict__ c_feat,
                        const float* __restrict__ g_feat,
                        const float* __restrict__ Wm,
                        const float* __restrict__ Wd,
                        const float* __restrict__ Wp) {
    int i = blockIdx.x * blockDim.x + threadIdx.x;
    const int NA = M_PAD * DD;
    if (i < NA) {
        int m = i >> 6;
        float v = (m < N_CELLS) ? c_feat[i] : 0.0f;
        __nv_bfloat16 hi = __float2bfloat16(v);
        __nv_bfloat16 lo = __float2bfloat16(v - __bfloat162float(hi));
        g_Ahi[i] = hi;
        g_Alo[i] = lo;
    } else {
        int j = i - NA;
        if (j >= N_PAD * DD) return;
        int n = j >> 6;
        int k = j & 63;
        float v = 0.0f;
        if (n < N_COLS) {
            int gene = n / 3;
            int head = n - gene * 3;
            const float* W = (head == 0) ? Wm : (head == 1 ? Wd : Wp);
            v = g_feat[gene * DD + k] * W[k];
        }
        __nv_bfloat16 hi = __float2bfloat16(v);
        __nv_bfloat16 lo = __float2bfloat16(v - __bfloat162float(hi));
        g_Bhi[j] = hi;
        g_Blo[j] = lo;
    }
}

// ---------------- phase 1: HMMA GEMM  C = A @ B^T  (3-pass hi/lo) ------------
// CTA: 256 thr, tile 128x128, K=64. Warp grid 4(m) x 2(n); warp tile 32x64.
__global__ __launch_bounds__(256) void zinb_gemm() {
    extern __shared__ __align__(16) char sm[];
    const int OAH = 0, OAL = 18432, OBH = 36864, OBL = 55296;  // 128*144 each

    const int tid   = threadIdx.x;
    const int ntile = blockIdx.x;
    const int mtile = blockIdx.y;

    // Cooperative gmem->smem: 4 matrices x 128 rows x 8 uint4.
    const uint4* Ah4 = (const uint4*)g_Ahi + (size_t)mtile * 1024;
    const uint4* Al4 = (const uint4*)g_Alo + (size_t)mtile * 1024;
    const uint4* Bh4 = (const uint4*)g_Bhi + (size_t)ntile * 1024;
    const uint4* Bl4 = (const uint4*)g_Blo + (size_t)ntile * 1024;
    #pragma unroll
    for (int it = 0; it < 4; it++) {
        int idx = tid + it * 256;         // 0..1023
        int row = idx >> 3, c = idx & 7;
        int off = row * SA + c * 16;
        *(uint4*)(sm + OAH + off) = Ah4[idx];
        *(uint4*)(sm + OAL + off) = Al4[idx];
        *(uint4*)(sm + OBH + off) = Bh4[idx];
        *(uint4*)(sm + OBL + off) = Bl4[idx];
    }
    __syncthreads();

    const uint32_t sbase = smem_u32(sm);
    const int wid = tid >> 5, lane = tid & 31;
    const int wm = wid & 3, wn = wid >> 2;
    const int lr = lane & 15, lc = lane >> 4;

    float acc[2][8][4];
    #pragma unroll
    for (int i = 0; i < 2; i++)
        #pragma unroll
        for (int j = 0; j < 8; j++)
            #pragma unroll
            for (int q = 0; q < 4; q++) acc[i][j][q] = 0.0f;

    #pragma unroll
    for (int pass = 0; pass < 3; pass++) {
        const uint32_t abase = sbase + (pass == 2 ? OAL : OAH);
        const uint32_t bbase = sbase + (pass == 1 ? OBL : OBH);
        #pragma unroll
        for (int k = 0; k < 4; k++) {
            uint32_t a[2][4], b[4][4];
            #pragma unroll
            for (int mt = 0; mt < 2; mt++)
                ldm4(a[mt], abase + (wm * 32 + mt * 16 + lr) * SA + k * 32 + lc * 16);
            #pragma unroll
            for (int np = 0; np < 4; np++)
                ldm4(b[np], bbase + (wn * 64 + np * 16 + lr) * SA + k * 32 + lc * 16);
            #pragma unroll
            for (int mt = 0; mt < 2; mt++)
                #pragma unroll
                for (int nt = 0; nt < 8; nt++)
                    mma16816(acc[mt][nt], a[mt],
                             b[nt >> 1][nt & 1], b[nt >> 1][(nt & 1) + 2]);
        }
    }

    // Store: row-major C, stride N_PAD.
    #pragma unroll
    for (int mt = 0; mt < 2; mt++) {
        const int r0 = mtile * TILE + wm * 32 + mt * 16 + (lane >> 2);
        #pragma unroll
        for (int nt = 0; nt < 8; nt++) {
            const int c0 = ntile * TILE + wn * 64 + nt * 8 + (lane & 3) * 2;
            *(float2*)&g_C[(size_t)r0 * N_PAD + c0] =
                make_float2(acc[mt][nt][0], acc[mt][nt][1]);
            *(float2*)&g_C[(size_t)(r0 + 8) * N_PAD + c0] =
                make_float2(acc[mt][nt][2], acc[mt][nt][3]);
        }
    }
}

// ---------------- phase 2: per-edge gather + activations ---------------------
__global__ __launch_bounds__(256) void zinb_gather(
    const int* __restrict__ src, const int* __restrict__ dst,
    const float* __restrict__ cs_factor, const float* __restrict__ gs_factor,
    const float* __restrict__ bm, const float* __restrict__ bd,
    const float* __restrict__ bp,
    float* __restrict__ out, int E)
{
    int e = blockIdx.x * blockDim.x + threadIdx.x;
    if (e >= E) return;
    const int s = __ldg(src + e);
    const int d = __ldg(dst + e);

    const float* row = g_C + (size_t)s * N_PAD + d * 3;
    const float sm = __ldg(row);
    const float sd = __ldg(row + 1);
    const float sp = __ldg(row + 2);

    const float gsv = __ldg(gs_factor + d);
    const float csv = __ldg(cs_factor + s);
    const float bmv = __ldg(bm), bdv = __ldg(bd), bpv = __ldg(bp);

    const float mu_ = 1.0f / (1.0f + expf(-(sm + bmv)));
    const float piv = 1.0f / (1.0f + expf(-(sp + bpv)));
    const float x = gsv * (sd + bdv);
    const float spv = fmaxf(x, 0.0f) + log1pf(expf(-fabsf(x)));
    const float dispv = fminf(fmaxf(spv, 1e-4f), 1e4f);
    const float muv = csv * fminf(fmaxf(expf(gsv * mu_) - 1.0f, 1e-5f), 1e6f);

    out[e] = muv;
    out[e + E] = dispv;
    out[e + 2 * (size_t)E] = piv;
}

// ---------------- launch -----------------------------------------------------
extern "C" void kernel_launch(void* const* d_in, const int* in_sizes, int n_in,
                              void* d_out, int out_size) {
    const float* c_feat    = (const float*)d_in[0];
    const float* g_feat    = (const float*)d_in[1];
    const float* cs_factor = (const float*)d_in[2];
    const float* gs_factor = (const float*)d_in[3];
    const int*   src       = (const int*)d_in[4];
    const int*   dst       = (const int*)d_in[5];
    const float* Wm        = (const float*)d_in[6];
    const float* bm        = (const float*)d_in[7];
    const float* Wd        = (const float*)d_in[8];
    const float* bd        = (const float*)d_in[9];
    const float* Wp        = (const float*)d_in[10];
    const float* bp        = (const float*)d_in[11];
    float* out = (float*)d_out;
    const int E = in_sizes[4];

    const int nPrep = (M_PAD + N_PAD) * DD;
    prep_AB<<<(nPrep + 255) / 256, 256>>>(c_feat, g_feat, Wm, Wd, Wp);

    const int dyn_bytes = 4 * 128 * SA;   // 73728
    cudaFuncSetAttribute(zinb_gemm, cudaFuncAttributeMaxDynamicSharedMemorySize,
                         dyn_bytes);
    dim3 grid(NTT, MT);
    zinb_gemm<<<grid, 256, dyn_bytes>>>();

    zinb_gather<<<(E + 255) / 256, 256>>>(src, dst, cs_factor, gs_factor,
                                          bm, bd, bp, out, E);
}

// round 6
// speedup vs baseline: 1.4465x; 1.0571x over previous
#include <cuda_runtime.h>
#include <cuda_fp16.h>
#include <cstdint>

#define N_CELLS 10000
#define N_GENES 2000
#define DD      64
#define TILE    128
#define MT      79                  // ceil(10000/128)
#define NTT     47                  // 6016/128
#define M_PAD   (MT * TILE)         // 10112
#define N_COLS  (3 * N_GENES)       // 6000  (n = gene*3 + head)
#define N_PAD   (NTT * TILE)        // 6016
#define SA      144                 // smem row stride bytes (64 fp16 = 128B + 16B pad)

// ---------------- device scratch (static; no runtime allocation) ------------
__device__ __half g_Ah[M_PAD * DD];
__device__ __half g_Bh[N_PAD * DD];
__device__ __half g_Bl[N_PAD * DD];
__device__ float  g_C[(size_t)M_PAD * N_PAD];    // 243 MB, row-major [M_PAD][6016]

// ---------------- helpers ----------------------------------------------------
__device__ __forceinline__ uint32_t smem_u32(const void* p) {
    uint32_t a;
    asm("{ .reg .u64 t; cvta.to.shared.u64 t, %1; cvt.u32.u64 %0, t; }" : "=r"(a) : "l"(p));
    return a;
}

__device__ __forceinline__ void ldm4(uint32_t* r, uint32_t addr) {
    asm volatile("ldmatrix.sync.aligned.m8n8.x4.shared.b16 {%0,%1,%2,%3}, [%4];"
                 : "=r"(r[0]), "=r"(r[1]), "=r"(r[2]), "=r"(r[3]) : "r"(addr));
}

__device__ __forceinline__ void mma16816(float* c, const uint32_t* a,
                                         uint32_t b0, uint32_t b1) {
    asm volatile(
        "mma.sync.aligned.m16n8k16.row.col.f32.f16.f16.f32 "
        "{%0,%1,%2,%3}, {%4,%5,%6,%7}, {%8,%9}, {%0,%1,%2,%3};"
        : "+f"(c[0]), "+f"(c[1]), "+f"(c[2]), "+f"(c[3])
        : "r"(a[0]), "r"(a[1]), "r"(a[2]), "r"(a[3]), "r"(b0), "r"(b1));
}

// ---------------- phase 0: prep (A fp16; B fp16 hi/lo) -----------------------
__global__ void prep_AB(const float* __restrict__ c_feat,
                        const float* __restrict__ g_feat,
                        const float* __restrict__ Wm,
                        const float* __restrict__ Wd,
                        const float* __restrict__ Wp) {
    int i = blockIdx.x * blockDim.x + threadIdx.x;
    const int NA = M_PAD * DD;
    if (i < NA) {
        int m = i >> 6;
        float v = (m < N_CELLS) ? c_feat[i] : 0.0f;
        g_Ah[i] = __float2half_rn(v);
    } else {
        int j = i - NA;
        if (j >= N_PAD * DD) return;
        int n = j >> 6;
        int k = j & 63;
        float v = 0.0f;
        if (n < N_COLS) {
            int gene = n / 3;
            int head = n - gene * 3;
            const float* W = (head == 0) ? Wm : (head == 1 ? Wd : Wp);
            v = g_feat[gene * DD + k] * W[k];
        }
        __half hi = __float2half_rn(v);
        __half lo = __float2half_rn(v - __half2float(hi));
        g_Bh[j] = hi;
        g_Bl[j] = lo;
    }
}

// ---------------- phase 1: HMMA GEMM  C = A @ B^T  (2-pass: Ah*Bh + Ah*Bl) ---
// CTA: 256 thr, tile 128x128, K=64. Warp grid 4(m) x 2(n); warp tile 32x64.
__global__ __launch_bounds__(256) void zinb_gemm() {
    extern __shared__ __align__(16) char sm[];
    const int OA = 0, OBH = 18432, OBL = 36864;  // 128*144 each

    const int tid   = threadIdx.x;
    const int ntile = blockIdx.x;
    const int mtile = blockIdx.y;

    // Cooperative gmem->smem: 3 matrices x 128 rows x 8 uint4.
    const uint4* A4  = (const uint4*)g_Ah + (size_t)mtile * 1024;
    const uint4* Bh4 = (const uint4*)g_Bh + (size_t)ntile * 1024;
    const uint4* Bl4 = (const uint4*)g_Bl + (size_t)ntile * 1024;
    #pragma unroll
    for (int it = 0; it < 4; it++) {
        int idx = tid + it * 256;         // 0..1023
        int row = idx >> 3, c = idx & 7;
        int off = row * SA + c * 16;
        *(uint4*)(sm + OA  + off) = A4[idx];
        *(uint4*)(sm + OBH + off) = Bh4[idx];
        *(uint4*)(sm + OBL + off) = Bl4[idx];
    }
    __syncthreads();

    const uint32_t sbase = smem_u32(sm);
    const int wid = tid >> 5, lane = tid & 31;
    const int wm = wid & 3, wn = wid >> 2;
    const int lr = lane & 15, lc = lane >> 4;

    float acc[2][8][4];
    #pragma unroll
    for (int i = 0; i < 2; i++)
        #pragma unroll
        for (int j = 0; j < 8; j++)
            #pragma unroll
            for (int q = 0; q < 4; q++) acc[i][j][q] = 0.0f;

    #pragma unroll
    for (int k = 0; k < 4; k++) {
        uint32_t a[2][4];
        #pragma unroll
        for (int mt = 0; mt < 2; mt++)
            ldm4(a[mt], sbase + OA + (wm * 32 + mt * 16 + lr) * SA + k * 32 + lc * 16);

        // pass 1: A * B_hi
        {
            uint32_t b[4][4];
            #pragma unroll
            for (int np = 0; np < 4; np++)
                ldm4(b[np], sbase + OBH + (wn * 64 + np * 16 + lr) * SA + k * 32 + lc * 16);
            #pragma unroll
            for (int mt = 0; mt < 2; mt++)
                #pragma unroll
                for (int nt = 0; nt < 8; nt++)
                    mma16816(acc[mt][nt], a[mt],
                             b[nt >> 1][nt & 1], b[nt >> 1][(nt & 1) + 2]);
        }
        // pass 2: A * B_lo
        {
            uint32_t b[4][4];
            #pragma unroll
            for (int np = 0; np < 4; np++)
                ldm4(b[np], sbase + OBL + (wn * 64 + np * 16 + lr) * SA + k * 32 + lc * 16);
            #pragma unroll
            for (int mt = 0; mt < 2; mt++)
                #pragma unroll
                for (int nt = 0; nt < 8; nt++)
                    mma16816(acc[mt][nt], a[mt],
                             b[nt >> 1][nt & 1], b[nt >> 1][(nt & 1) + 2]);
        }
    }

    // Store: row-major C, stride N_PAD.
    #pragma unroll
    for (int mt = 0; mt < 2; mt++) {
        const int r0 = mtile * TILE + wm * 32 + mt * 16 + (lane >> 2);
        #pragma unroll
        for (int nt = 0; nt < 8; nt++) {
            const int c0 = ntile * TILE + wn * 64 + nt * 8 + (lane & 3) * 2;
            *(float2*)&g_C[(size_t)r0 * N_PAD + c0] =
                make_float2(acc[mt][nt][0], acc[mt][nt][1]);
            *(float2*)&g_C[(size_t)(r0 + 8) * N_PAD + c0] =
                make_float2(acc[mt][nt][2], acc[mt][nt][3]);
        }
    }
}

// ---------------- phase 2: per-edge gather + activations ---------------------
__global__ __launch_bounds__(256) void zinb_gather(
    const int* __restrict__ src, const int* __restrict__ dst,
    const float* __restrict__ cs_factor, const float* __restrict__ gs_factor,
    const float* __restrict__ bm, const float* __restrict__ bd,
    const float* __restrict__ bp,
    float* __restrict__ out, int E)
{
    int e = blockIdx.x * blockDim.x + threadIdx.x;
    if (e >= E) return;
    const int s = __ldg(src + e);
    const int d = __ldg(dst + e);

    const float* row = g_C + (size_t)s * N_PAD + d * 3;
    const float sm = __ldcg(row);
    const float sd = __ldcg(row + 1);
    const float sp = __ldcg(row + 2);

    const float gsv = __ldg(gs_factor + d);
    const float csv = __ldg(cs_factor + s);
    const float bmv = __ldg(bm), bdv = __ldg(bd), bpv = __ldg(bp);

    const float mu_ = 1.0f / (1.0f + __expf(-(sm + bmv)));
    const float piv = 1.0f / (1.0f + __expf(-(sp + bpv)));
    const float x = gsv * (sd + bdv);
    const float spv = fmaxf(x, 0.0f) + log1pf(__expf(-fabsf(x)));
    const float dispv = fminf(fmaxf(spv, 1e-4f), 1e4f);
    const float muv = csv * fminf(fmaxf(__expf(gsv * mu_) - 1.0f, 1e-5f), 1e6f);

    out[e] = muv;
    out[e + E] = dispv;
    out[e + 2 * (size_t)E] = piv;
}

// ---------------- launch -----------------------------------------------------
extern "C" void kernel_launch(void* const* d_in, const int* in_sizes, int n_in,
                              void* d_out, int out_size) {
    const float* c_feat    = (const float*)d_in[0];
    const float* g_feat    = (const float*)d_in[1];
    const float* cs_factor = (const float*)d_in[2];
    const float* gs_factor = (const float*)d_in[3];
    const int*   src       = (const int*)d_in[4];
    const int*   dst       = (const int*)d_in[5];
    const float* Wm        = (const float*)d_in[6];
    const float* bm        = (const float*)d_in[7];
    const float* Wd        = (const float*)d_in[8];
    const float* bd        = (const float*)d_in[9];
    const float* Wp        = (const float*)d_in[10];
    const float* bp        = (const float*)d_in[11];
    float* out = (float*)d_out;
    const int E = in_sizes[4];

    const int nPrep = (M_PAD + N_PAD) * DD;
    prep_AB<<<(nPrep + 255) / 256, 256>>>(c_feat, g_feat, Wm, Wd, Wp);

    const int dyn_bytes = 3 * 128 * SA;   // 55296
    cudaFuncSetAttribute(zinb_gemm, cudaFuncAttributeMaxDynamicSharedMemorySize,
                         dyn_bytes);
    dim3 grid(NTT, MT);
    zinb_gemm<<<grid, 256, dyn_bytes>>>();

    zinb_gather<<<(E + 255) / 256, 256>>>(src, dst, cs_factor, gs_factor,
                                          bm, bd, bp, out, E);
}

// round 7
// speedup vs baseline: 1.7051x; 1.1788x over previous
#include <cuda_runtime.h>
#include <cuda_fp16.h>
#include <cstdint>

#define N_CELLS 10000
#define N_GENES 2000
#define DD      64
#define TILE    128
#define MT      79                  // ceil(10000/128)
#define NTT     47                  // 6016/128
#define M_PAD   (MT * TILE)         // 10112
#define N_COLS  (3 * N_GENES)       // 6000  (n = gene*3 + head)
#define N_PAD   (NTT * TILE)        // 6016
#define SA      144                 // smem row stride bytes (64 fp16 = 128B + 16B pad)

// ---------------- device scratch (static; no runtime allocation) ------------
__device__ __half g_Ah[M_PAD * DD];
__device__ __half g_Bh[N_PAD * DD];
__device__ __half g_Bl[N_PAD * DD];
__device__ __half g_Ch[(size_t)M_PAD * N_PAD];   // 121.6 MB — fits in 126MB L2

// ---------------- helpers ----------------------------------------------------
__device__ __forceinline__ uint32_t smem_u32(const void* p) {
    uint32_t a;
    asm("{ .reg .u64 t; cvta.to.shared.u64 t, %1; cvt.u32.u64 %0, t; }" : "=r"(a) : "l"(p));
    return a;
}

__device__ __forceinline__ void ldm4(uint32_t* r, uint32_t addr) {
    asm volatile("ldmatrix.sync.aligned.m8n8.x4.shared.b16 {%0,%1,%2,%3}, [%4];"
                 : "=r"(r[0]), "=r"(r[1]), "=r"(r[2]), "=r"(r[3]) : "r"(addr));
}

__device__ __forceinline__ void mma16816(float* c, const uint32_t* a,
                                         uint32_t b0, uint32_t b1) {
    asm volatile(
        "mma.sync.aligned.m16n8k16.row.col.f32.f16.f16.f32 "
        "{%0,%1,%2,%3}, {%4,%5,%6,%7}, {%8,%9}, {%0,%1,%2,%3};"
        : "+f"(c[0]), "+f"(c[1]), "+f"(c[2]), "+f"(c[3])
        : "r"(a[0]), "r"(a[1]), "r"(a[2]), "r"(a[3]), "r"(b0), "r"(b1));
}

// ---------------- phase 0: prep (A fp16; B fp16 hi/lo) -----------------------
__global__ void prep_AB(const float* __restrict__ c_feat,
                        const float* __restrict__ g_feat,
                        const float* __restrict__ Wm,
                        const float* __restrict__ Wd,
                        const float* __restrict__ Wp) {
    int i = blockIdx.x * blockDim.x + threadIdx.x;
    const int NA = M_PAD * DD;
    if (i < NA) {
        int m = i >> 6;
        float v = (m < N_CELLS) ? c_feat[i] : 0.0f;
        g_Ah[i] = __float2half_rn(v);
    } else {
        int j = i - NA;
        if (j >= N_PAD * DD) return;
        int n = j >> 6;
        int k = j & 63;
        float v = 0.0f;
        if (n < N_COLS) {
            int gene = n / 3;
            int head = n - gene * 3;
            const float* W = (head == 0) ? Wm : (head == 1 ? Wd : Wp);
            v = g_feat[gene * DD + k] * W[k];
        }
        __half hi = __float2half_rn(v);
        __half lo = __float2half_rn(v - __half2float(hi));
        g_Bh[j] = hi;
        g_Bl[j] = lo;
    }
}

// ---------------- phase 1: HMMA GEMM  C = A @ B^T  (2-pass: Ah*Bh + Ah*Bl) ---
// CTA: 256 thr, tile 128x128, K=64. Warp grid 4(m) x 2(n); warp tile 32x64.
__global__ __launch_bounds__(256) void zinb_gemm() {
    extern __shared__ __align__(16) char sm[];
    const int OA = 0, OBH = 18432, OBL = 36864;  // 128*144 each

    const int tid   = threadIdx.x;
    const int ntile = blockIdx.x;
    const int mtile = blockIdx.y;

    // Cooperative gmem->smem: 3 matrices x 128 rows x 8 uint4.
    const uint4* A4  = (const uint4*)g_Ah + (size_t)mtile * 1024;
    const uint4* Bh4 = (const uint4*)g_Bh + (size_t)ntile * 1024;
    const uint4* Bl4 = (const uint4*)g_Bl + (size_t)ntile * 1024;
    #pragma unroll
    for (int it = 0; it < 4; it++) {
        int idx = tid + it * 256;         // 0..1023
        int row = idx >> 3, c = idx & 7;
        int off = row * SA + c * 16;
        *(uint4*)(sm + OA  + off) = A4[idx];
        *(uint4*)(sm + OBH + off) = Bh4[idx];
        *(uint4*)(sm + OBL + off) = Bl4[idx];
    }
    __syncthreads();

    const uint32_t sbase = smem_u32(sm);
    const int wid = tid >> 5, lane = tid & 31;
    const int wm = wid & 3, wn = wid >> 2;
    const int lr = lane & 15, lc = lane >> 4;

    float acc[2][8][4];
    #pragma unroll
    for (int i = 0; i < 2; i++)
        #pragma unroll
        for (int j = 0; j < 8; j++)
            #pragma unroll
            for (int q = 0; q < 4; q++) acc[i][j][q] = 0.0f;

    #pragma unroll
    for (int k = 0; k < 4; k++) {
        uint32_t a[2][4];
        #pragma unroll
        for (int mt = 0; mt < 2; mt++)
            ldm4(a[mt], sbase + OA + (wm * 32 + mt * 16 + lr) * SA + k * 32 + lc * 16);

        // pass 1: A * B_hi
        {
            uint32_t b[4][4];
            #pragma unroll
            for (int np = 0; np < 4; np++)
                ldm4(b[np], sbase + OBH + (wn * 64 + np * 16 + lr) * SA + k * 32 + lc * 16);
            #pragma unroll
            for (int mt = 0; mt < 2; mt++)
                #pragma unroll
                for (int nt = 0; nt < 8; nt++)
                    mma16816(acc[mt][nt], a[mt],
                             b[nt >> 1][nt & 1], b[nt >> 1][(nt & 1) + 2]);
        }
        // pass 2: A * B_lo
        {
            uint32_t b[4][4];
            #pragma unroll
            for (int np = 0; np < 4; np++)
                ldm4(b[np], sbase + OBL + (wn * 64 + np * 16 + lr) * SA + k * 32 + lc * 16);
            #pragma unroll
            for (int mt = 0; mt < 2; mt++)
                #pragma unroll
                for (int nt = 0; nt < 8; nt++)
                    mma16816(acc[mt][nt], a[mt],
                             b[nt >> 1][nt & 1], b[nt >> 1][(nt & 1) + 2]);
        }
    }

    // Store: row-major C (fp16), stride N_PAD. Even columns -> 4B-aligned half2.
    #pragma unroll
    for (int mt = 0; mt < 2; mt++) {
        const int r0 = mtile * TILE + wm * 32 + mt * 16 + (lane >> 2);
        #pragma unroll
        for (int nt = 0; nt < 8; nt++) {
            const int c0 = ntile * TILE + wn * 64 + nt * 8 + (lane & 3) * 2;
            *(__half2*)&g_Ch[(size_t)r0 * N_PAD + c0] =
                __floats2half2_rn(acc[mt][nt][0], acc[mt][nt][1]);
            *(__half2*)&g_Ch[(size_t)(r0 + 8) * N_PAD + c0] =
                __floats2half2_rn(acc[mt][nt][2], acc[mt][nt][3]);
        }
    }
}

// ---------------- phase 2: per-edge gather + activations ---------------------
__global__ __launch_bounds__(256) void zinb_gather(
    const int* __restrict__ src, const int* __restrict__ dst,
    const float* __restrict__ cs_factor, const float* __restrict__ gs_factor,
    const float* __restrict__ bm, const float* __restrict__ bd,
    const float* __restrict__ bp,
    float* __restrict__ out, int E)
{
    int e = blockIdx.x * blockDim.x + threadIdx.x;
    if (e >= E) return;
    const int s = __ldg(src + e);
    const int d = __ldg(dst + e);

    const __half* row = g_Ch + (size_t)s * N_PAD + d * 3;
    const float sm = __half2float(__ldg(row));
    const float sd = __half2float(__ldg(row + 1));
    const float sp = __half2float(__ldg(row + 2));

    const float gsv = __ldg(gs_factor + d);
    const float csv = __ldg(cs_factor + s);
    const float bmv = __ldg(bm), bdv = __ldg(bd), bpv = __ldg(bp);

    const float mu_ = 1.0f / (1.0f + __expf(-(sm + bmv)));
    const float piv = 1.0f / (1.0f + __expf(-(sp + bpv)));
    const float x = gsv * (sd + bdv);
    const float spv = fmaxf(x, 0.0f) + log1pf(__expf(-fabsf(x)));
    const float dispv = fminf(fmaxf(spv, 1e-4f), 1e4f);
    const float muv = csv * fminf(fmaxf(__expf(gsv * mu_) - 1.0f, 1e-5f), 1e6f);

    out[e] = muv;
    out[e + E] = dispv;
    out[e + 2 * (size_t)E] = piv;
}

// ---------------- launch -----------------------------------------------------
extern "C" void kernel_launch(void* const* d_in, const int* in_sizes, int n_in,
                              void* d_out, int out_size) {
    const float* c_feat    = (const float*)d_in[0];
    const float* g_feat    = (const float*)d_in[1];
    const float* cs_factor = (const float*)d_in[2];
    const float* gs_factor = (const float*)d_in[3];
    const int*   src       = (const int*)d_in[4];
    const int*   dst       = (const int*)d_in[5];
    const float* Wm        = (const float*)d_in[6];
    const float* bm        = (const float*)d_in[7];
    const float* Wd        = (const float*)d_in[8];
    const float* bd        = (const float*)d_in[9];
    const float* Wp        = (const float*)d_in[10];
    const float* bp        = (const float*)d_in[11];
    float* out = (float*)d_out;
    const int E = in_sizes[4];

    const int nPrep = (M_PAD + N_PAD) * DD;
    prep_AB<<<(nPrep + 255) / 256, 256>>>(c_feat, g_feat, Wm, Wd, Wp);

    const int dyn_bytes = 3 * 128 * SA;   // 55296
    cudaFuncSetAttribute(zinb_gemm, cudaFuncAttributeMaxDynamicSharedMemorySize,
                         dyn_bytes);
    dim3 grid(NTT, MT);
    zinb_gemm<<<grid, 256, dyn_bytes>>>();

    zinb_gather<<<(E + 255) / 256, 256>>>(src, dst, cs_factor, gs_factor,
                                          bm, bd, bp, out, E);
}

// round 10
// speedup vs baseline: 1.7305x; 1.0149x over previous
#include <cuda_runtime.h>
#include <cuda_fp16.h>
#include <cstdint>

#define N_CELLS 10000
#define N_GENES 2000
#define DD      64
#define TILE    128
#define MT      79                  // ceil(10000/128)
#define NTT     47                  // 6016/128
#define M_PAD   (MT * TILE)         // 10112
#define N_COLS  (3 * N_GENES)       // 6000  (n = gene*3 + head)
#define N_PAD   (NTT * TILE)        // 6016
#define SA      144                 // smem row stride bytes (64 fp16 = 128B + 16B pad)

// ---------------- device scratch (static; no runtime allocation) ------------
__device__ __half g_Ah[M_PAD * DD];
__device__ __half g_Bh[N_PAD * DD];
__device__ __half g_Bl[N_PAD * DD];
__device__ __half g_Ch[(size_t)M_PAD * N_PAD];   // 121.6 MB — L2-resident target

// ---------------- helpers ----------------------------------------------------
__device__ __forceinline__ uint32_t smem_u32(const void* p) {
    uint32_t a;
    asm("{ .reg .u64 t; cvta.to.shared.u64 t, %1; cvt.u32.u64 %0, t; }" : "=r"(a) : "l"(p));
    return a;
}

__device__ __forceinline__ void ldm4(uint32_t* r, uint32_t addr) {
    asm volatile("ldmatrix.sync.aligned.m8n8.x4.shared.b16 {%0,%1,%2,%3}, [%4];"
                 : "=r"(r[0]), "=r"(r[1]), "=r"(r[2]), "=r"(r[3]) : "r"(addr));
}

__device__ __forceinline__ void mma16816(float* c, const uint32_t* a,
                                         uint32_t b0, uint32_t b1) {
    asm volatile(
        "mma.sync.aligned.m16n8k16.row.col.f32.f16.f16.f32 "
        "{%0,%1,%2,%3}, {%4,%5,%6,%7}, {%8,%9}, {%0,%1,%2,%3};"
        : "+f"(c[0]), "+f"(c[1]), "+f"(c[2]), "+f"(c[3])
        : "r"(a[0]), "r"(a[1]), "r"(a[2]), "r"(a[3]), "r"(b0), "r"(b1));
}

// Access-policy register: fraction 1.0 of L2 at evict_last priority.
__device__ __forceinline__ uint64_t mk_pol_evict_last() {
    uint64_t p;
    asm("createpolicy.fractional.L2::evict_last.b64 %0, 1.0;" : "=l"(p));
    return p;
}

// C store: keep in L2 with evict_last priority (via cache_hint policy).
__device__ __forceinline__ void st_c_el(__half* p, __half2 v, uint64_t pol) {
    asm volatile("st.global.L2::cache_hint.u32 [%0], %1, %2;"
                 :: "l"(p), "r"(*(uint32_t*)&v), "l"(pol) : "memory");
}

// C gather load: non-coherent, evict_last priority (via cache_hint policy).
__device__ __forceinline__ float ld_c_el(const __half* p, uint64_t pol) {
    unsigned short v;
    asm volatile("ld.global.nc.L2::cache_hint.u16 %0, [%1], %2;"
                 : "=h"(v) : "l"(p), "l"(pol));
    return __half2float(*reinterpret_cast<__half*>(&v));
}

// ---------------- phase 0: prep (A fp16; B fp16 hi/lo) -----------------------
__global__ void prep_AB(const float* __restrict__ c_feat,
                        const float* __restrict__ g_feat,
                        const float* __restrict__ Wm,
                        const float* __restrict__ Wd,
                        const float* __restrict__ Wp) {
    int i = blockIdx.x * blockDim.x + threadIdx.x;
    const int NA = M_PAD * DD;
    if (i < NA) {
        int m = i >> 6;
        float v = (m < N_CELLS) ? c_feat[i] : 0.0f;
        g_Ah[i] = __float2half_rn(v);
    } else {
        int j = i - NA;
        if (j >= N_PAD * DD) return;
        int n = j >> 6;
        int k = j & 63;
        float v = 0.0f;
        if (n < N_COLS) {
            int gene = n / 3;
            int head = n - gene * 3;
            const float* W = (head == 0) ? Wm : (head == 1 ? Wd : Wp);
            v = g_feat[gene * DD + k] * W[k];
        }
        __half hi = __float2half_rn(v);
        __half lo = __float2half_rn(v - __half2float(hi));
        g_Bh[j] = hi;
        g_Bl[j] = lo;
    }
}

// ---------------- phase 1: HMMA GEMM  C = A @ B^T  (2-pass: Ah*Bh + Ah*Bl) ---
__global__ __launch_bounds__(256) void zinb_gemm() {
    extern __shared__ __align__(16) char sm[];
    const int OA = 0, OBH = 18432, OBL = 36864;  // 128*144 each

    const int tid   = threadIdx.x;
    const int ntile = blockIdx.x;
    const int mtile = blockIdx.y;

    const uint4* A4  = (const uint4*)g_Ah + (size_t)mtile * 1024;
    const uint4* Bh4 = (const uint4*)g_Bh + (size_t)ntile * 1024;
    const uint4* Bl4 = (const uint4*)g_Bl + (size_t)ntile * 1024;
    #pragma unroll
    for (int it = 0; it < 4; it++) {
        int idx = tid + it * 256;         // 0..1023
        int row = idx >> 3, c = idx & 7;
        int off = row * SA + c * 16;
        *(uint4*)(sm + OA  + off) = A4[idx];
        *(uint4*)(sm + OBH + off) = Bh4[idx];
        *(uint4*)(sm + OBL + off) = Bl4[idx];
    }
    __syncthreads();

    const uint32_t sbase = smem_u32(sm);
    const int wid = tid >> 5, lane = tid & 31;
    const int wm = wid & 3, wn = wid >> 2;
    const int lr = lane & 15, lc = lane >> 4;

    float acc[2][8][4];
    #pragma unroll
    for (int i = 0; i < 2; i++)
        #pragma unroll
        for (int j = 0; j < 8; j++)
            #pragma unroll
            for (int q = 0; q < 4; q++) acc[i][j][q] = 0.0f;

    #pragma unroll
    for (int k = 0; k < 4; k++) {
        uint32_t a[2][4];
        #pragma unroll
        for (int mt = 0; mt < 2; mt++)
            ldm4(a[mt], sbase + OA + (wm * 32 + mt * 16 + lr) * SA + k * 32 + lc * 16);

        {   // pass 1: A * B_hi
            uint32_t b[4][4];
            #pragma unroll
            for (int np = 0; np < 4; np++)
                ldm4(b[np], sbase + OBH + (wn * 64 + np * 16 + lr) * SA + k * 32 + lc * 16);
            #pragma unroll
            for (int mt = 0; mt < 2; mt++)
                #pragma unroll
                for (int nt = 0; nt < 8; nt++)
                    mma16816(acc[mt][nt], a[mt],
                             b[nt >> 1][nt & 1], b[nt >> 1][(nt & 1) + 2]);
        }
        {   // pass 2: A * B_lo
            uint32_t b[4][4];
            #pragma unroll
            for (int np = 0; np < 4; np++)
                ldm4(b[np], sbase + OBL + (wn * 64 + np * 16 + lr) * SA + k * 32 + lc * 16);
            #pragma unroll
            for (int mt = 0; mt < 2; mt++)
                #pragma unroll
                for (int nt = 0; nt < 8; nt++)
                    mma16816(acc[mt][nt], a[mt],
                             b[nt >> 1][nt & 1], b[nt >> 1][(nt & 1) + 2]);
        }
    }

    // Store: row-major C (fp16), stride N_PAD; evict_last so C survives in L2.
    const uint64_t pol = mk_pol_evict_last();
    #pragma unroll
    for (int mt = 0; mt < 2; mt++) {
        const int r0 = mtile * TILE + wm * 32 + mt * 16 + (lane >> 2);
        #pragma unroll
        for (int nt = 0; nt < 8; nt++) {
            const int c0 = ntile * TILE + wn * 64 + nt * 8 + (lane & 3) * 2;
            st_c_el(&g_Ch[(size_t)r0 * N_PAD + c0],
                    __floats2half2_rn(acc[mt][nt][0], acc[mt][nt][1]), pol);
            st_c_el(&g_Ch[(size_t)(r0 + 8) * N_PAD + c0],
                    __floats2half2_rn(acc[mt][nt][2], acc[mt][nt][3]), pol);
        }
    }
}

// ---------------- phase 2: per-edge gather + activations ---------------------
// 2 edges per thread (split-halves for coalescing); streaming hints on
// idx/out so C keeps L2 residency.
__global__ __launch_bounds__(256) void zinb_gather(
    const int* __restrict__ src, const int* __restrict__ dst,
    const float* __restrict__ cs_factor, const float* __restrict__ gs_factor,
    const float* __restrict__ bm, const float* __restrict__ bd,
    const float* __restrict__ bp,
    float* __restrict__ out, int E)
{
    const int half = (E + 1) >> 1;
    const int t = blockIdx.x * blockDim.x + threadIdx.x;
    if (t >= half) return;
    const int e0 = t;
    const int e1 = t + half;
    const bool v1 = (e1 < E);

    const int s0 = __ldcs(src + e0);
    const int d0 = __ldcs(dst + e0);
    const int s1 = v1 ? __ldcs(src + e1) : 0;
    const int d1 = v1 ? __ldcs(dst + e1) : 0;

    const __half* r0 = g_Ch + (size_t)s0 * N_PAD + d0 * 3;
    const __half* r1 = g_Ch + (size_t)s1 * N_PAD + d1 * 3;

    const uint64_t pol = mk_pol_evict_last();

    // 6 independent loads → MLP for latency hiding.
    const float sm0 = ld_c_el(r0, pol);
    const float sd0 = ld_c_el(r0 + 1, pol);
    const float sp0 = ld_c_el(r0 + 2, pol);
    const float sm1 = ld_c_el(r1, pol);
    const float sd1 = ld_c_el(r1 + 1, pol);
    const float sp1 = ld_c_el(r1 + 2, pol);

    const float gs0 = __ldg(gs_factor + d0);
    const float cs0 = __ldg(cs_factor + s0);
    const float gs1 = __ldg(gs_factor + d1);
    const float cs1 = __ldg(cs_factor + s1);
    const float bmv = __ldg(bm), bdv = __ldg(bd), bpv = __ldg(bp);

    {
        const float mu_ = 1.0f / (1.0f + __expf(-(sm0 + bmv)));
        const float piv = 1.0f / (1.0f + __expf(-(sp0 + bpv)));
        const float x = gs0 * (sd0 + bdv);
        const float spv = fmaxf(x, 0.0f) + log1pf(__expf(-fabsf(x)));
        const float dispv = fminf(fmaxf(spv, 1e-4f), 1e4f);
        const float muv = cs0 * fminf(fmaxf(__expf(gs0 * mu_) - 1.0f, 1e-5f), 1e6f);
        __stcs(out + e0, muv);
        __stcs(out + e0 + E, dispv);
        __stcs(out + e0 + 2 * (size_t)E, piv);
    }
    if (v1) {
        const float mu_ = 1.0f / (1.0f + __expf(-(sm1 + bmv)));
        const float piv = 1.0f / (1.0f + __expf(-(sp1 + bpv)));
        const float x = gs1 * (sd1 + bdv);
        const float spv = fmaxf(x, 0.0f) + log1pf(__expf(-fabsf(x)));
        const float dispv = fminf(fmaxf(spv, 1e-4f), 1e4f);
        const float muv = cs1 * fminf(fmaxf(__expf(gs1 * mu_) - 1.0f, 1e-5f), 1e6f);
        __stcs(out + e1, muv);
        __stcs(out + e1 + E, dispv);
        __stcs(out + e1 + 2 * (size_t)E, piv);
    }
}

// ---------------- launch -----------------------------------------------------
extern "C" void kernel_launch(void* const* d_in, const int* in_sizes, int n_in,
                              void* d_out, int out_size) {
    const float* c_feat    = (const float*)d_in[0];
    const float* g_feat    = (const float*)d_in[1];
    const float* cs_factor = (const float*)d_in[2];
    const float* gs_factor = (const float*)d_in[3];
    const int*   src       = (const int*)d_in[4];
    const int*   dst       = (const int*)d_in[5];
    const float* Wm        = (const float*)d_in[6];
    const float* bm        = (const float*)d_in[7];
    const float* Wd        = (const float*)d_in[8];
    const float* bd        = (const float*)d_in[9];
    const float* Wp        = (const float*)d_in[10];
    const float* bp        = (const float*)d_in[11];
    float* out = (float*)d_out;
    const int E = in_sizes[4];

    const int nPrep = (M_PAD + N_PAD) * DD;
    prep_AB<<<(nPrep + 255) / 256, 256>>>(c_feat, g_feat, Wm, Wd, Wp);

    const int dyn_bytes = 3 * 128 * SA;   // 55296
    cudaFuncSetAttribute(zinb_gemm, cudaFuncAttributeMaxDynamicSharedMemorySize,
                         dyn_bytes);
    dim3 grid(NTT, MT);
    zinb_gemm<<<grid, 256, dyn_bytes>>>();

    const int half = (E + 1) >> 1;
    zinb_gather<<<(half + 255) / 256, 256>>>(src, dst, cs_factor, gs_factor,
                                             bm, bd, bp, out, E);
}

// round 11
// speedup vs baseline: 1.9641x; 1.1350x over previous
#include <cuda_runtime.h>
#include <cuda_fp16.h>
#include <cstdint>

#define N_CELLS 10000
#define N_GENES 2000
#define DD      64
#define TILE    128
#define MT      79                  // ceil(10000/128)
#define NTT     47                  // 6016/128
#define MG      8                   // mtiles per CTA
#define NGRP    10                  // ceil(79/8)
#define M_PAD   (MT * TILE)         // 10112
#define N_COLS  (3 * N_GENES)       // 6000  (n = gene*3 + head)
#define N_PAD   (NTT * TILE)        // 6016
#define SA      144                 // smem row stride bytes

// ---------------- device scratch (static; no runtime allocation) ------------
__device__ __half g_Ah[M_PAD * DD];
__device__ __half g_Bh[N_PAD * DD];
__device__ __half g_Ch[(size_t)M_PAD * N_PAD];   // 121.6 MB

// ---------------- helpers ----------------------------------------------------
__device__ __forceinline__ uint32_t smem_u32(const void* p) {
    uint32_t a;
    asm("{ .reg .u64 t; cvta.to.shared.u64 t, %1; cvt.u32.u64 %0, t; }" : "=r"(a) : "l"(p));
    return a;
}

__device__ __forceinline__ void ldm4(uint32_t* r, uint32_t addr) {
    asm volatile("ldmatrix.sync.aligned.m8n8.x4.shared.b16 {%0,%1,%2,%3}, [%4];"
                 : "=r"(r[0]), "=r"(r[1]), "=r"(r[2]), "=r"(r[3]) : "r"(addr));
}

__device__ __forceinline__ void mma16816(float* c, const uint32_t* a,
                                         uint32_t b0, uint32_t b1) {
    asm volatile(
        "mma.sync.aligned.m16n8k16.row.col.f32.f16.f16.f32 "
        "{%0,%1,%2,%3}, {%4,%5,%6,%7}, {%8,%9}, {%0,%1,%2,%3};"
        : "+f"(c[0]), "+f"(c[1]), "+f"(c[2]), "+f"(c[3])
        : "r"(a[0]), "r"(a[1]), "r"(a[2]), "r"(a[3]), "r"(b0), "r"(b1));
}

__device__ __forceinline__ uint64_t mk_pol_evict_last() {
    uint64_t p;
    asm("createpolicy.fractional.L2::evict_last.b64 %0, 1.0;" : "=l"(p));
    return p;
}

__device__ __forceinline__ void st_c_el(__half* p, __half2 v, uint64_t pol) {
    asm volatile("st.global.L2::cache_hint.u32 [%0], %1, %2;"
                 :: "l"(p), "r"(*(uint32_t*)&v), "l"(pol) : "memory");
}

__device__ __forceinline__ uint32_t ld_c32_el(const uint32_t* p, uint64_t pol) {
    uint32_t v;
    asm volatile("ld.global.nc.L2::cache_hint.u32 %0, [%1], %2;"
                 : "=r"(v) : "l"(p), "l"(pol));
    return v;
}

// ---------------- phase 0: prep (A fp16; B fp16) -----------------------------
__global__ void prep_AB(const float* __restrict__ c_feat,
                        const float* __restrict__ g_feat,
                        const float* __restrict__ Wm,
                        const float* __restrict__ Wd,
                        const float* __restrict__ Wp) {
    int i = blockIdx.x * blockDim.x + threadIdx.x;
    const int NA = M_PAD * DD;
    if (i < NA) {
        int m = i >> 6;
        float v = (m < N_CELLS) ? c_feat[i] : 0.0f;
        g_Ah[i] = __float2half_rn(v);
    } else {
        int j = i - NA;
        if (j >= N_PAD * DD) return;
        int n = j >> 6;
        int k = j & 63;
        float v = 0.0f;
        if (n < N_COLS) {
            int gene = n / 3;
            int head = n - gene * 3;
            const float* W = (head == 0) ? Wm : (head == 1 ? Wd : Wp);
            v = g_feat[gene * DD + k] * W[k];
        }
        g_Bh[j] = __float2half_rn(v);
    }
}

// ---------------- phase 1: HMMA GEMM  C = A @ B^T  (single fp16 pass) --------
// Grid (NTT, NGRP). Each CTA: B tile resident (smem + reg fragments),
// loops MG mtiles with double-buffered A. Warp tile 32(m) x 64(n).
__global__ __launch_bounds__(256) void zinb_gemm() {
    extern __shared__ __align__(16) char sm[];
    const int OB = 0, OA0 = 18432, OA1 = 36864;   // 128*144 each

    const int tid   = threadIdx.x;
    const int ntile = blockIdx.x;
    const int mgrp  = blockIdx.y;
    const int m0    = mgrp * MG;

    // Cooperative load: B tile + first A tile.
    {
        const uint4* B4 = (const uint4*)g_Bh + (size_t)ntile * 1024;
        const uint4* A4 = (const uint4*)g_Ah + (size_t)m0 * 1024;
        #pragma unroll
        for (int it = 0; it < 4; it++) {
            int idx = tid + it * 256;       // 0..1023
            int row = idx >> 3, c = idx & 7;
            int off = row * SA + c * 16;
            *(uint4*)(sm + OB + off) = B4[idx];
            *(uint4*)(sm + OA0 + off) = A4[idx];
        }
    }
    __syncthreads();

    const uint32_t sbase = smem_u32(sm);
    const int wid = tid >> 5, lane = tid & 31;
    const int wm = wid & 3, wn = wid >> 2;
    const int lr = lane & 15, lc = lane >> 4;

    // Hoist B fragments into registers (loop-invariant across mtiles).
    uint32_t bfrag[4][4][4];   // [k][np][reg]
    #pragma unroll
    for (int k = 0; k < 4; k++)
        #pragma unroll
        for (int np = 0; np < 4; np++)
            ldm4(bfrag[k][np],
                 sbase + OB + (wn * 64 + np * 16 + lr) * SA + k * 32 + lc * 16);

    const uint64_t pol = mk_pol_evict_last();

    for (int mi = 0; mi < MG; mi++) {
        const int mtile = m0 + mi;
        if (mtile >= MT) break;

        // Prefetch next A tile into the other buffer (no readers there).
        const int nmt = mtile + 1;
        if (mi + 1 < MG && nmt < MT) {
            const uint4* A4 = (const uint4*)g_Ah + (size_t)nmt * 1024;
            char* dst = sm + ((mi & 1) ? OA0 : OA1);
            #pragma unroll
            for (int it = 0; it < 4; it++) {
                int idx = tid + it * 256;
                int row = idx >> 3, c = idx & 7;
                *(uint4*)(dst + row * SA + c * 16) = A4[idx];
            }
        }

        const uint32_t abase = sbase + ((mi & 1) ? OA1 : OA0);

        float acc[2][8][4];
        #pragma unroll
        for (int i = 0; i < 2; i++)
            #pragma unroll
            for (int j = 0; j < 8; j++)
                #pragma unroll
                for (int q = 0; q < 4; q++) acc[i][j][q] = 0.0f;

        #pragma unroll
        for (int k = 0; k < 4; k++) {
            uint32_t a[2][4];
            #pragma unroll
            for (int mt = 0; mt < 2; mt++)
                ldm4(a[mt], abase + (wm * 32 + mt * 16 + lr) * SA + k * 32 + lc * 16);
            #pragma unroll
            for (int mt = 0; mt < 2; mt++)
                #pragma unroll
                for (int nt = 0; nt < 8; nt++)
                    mma16816(acc[mt][nt], a[mt],
                             bfrag[k][nt >> 1][nt & 1], bfrag[k][nt >> 1][(nt & 1) + 2]);
        }

        // Store C tile (fp16, evict_last).
        #pragma unroll
        for (int mt = 0; mt < 2; mt++) {
            const int r0 = mtile * TILE + wm * 32 + mt * 16 + (lane >> 2);
            #pragma unroll
            for (int nt = 0; nt < 8; nt++) {
                const int c0 = ntile * TILE + wn * 64 + nt * 8 + (lane & 3) * 2;
                st_c_el(&g_Ch[(size_t)r0 * N_PAD + c0],
                        __floats2half2_rn(acc[mt][nt][0], acc[mt][nt][1]), pol);
                st_c_el(&g_Ch[(size_t)(r0 + 8) * N_PAD + c0],
                        __floats2half2_rn(acc[mt][nt][2], acc[mt][nt][3]), pol);
            }
        }
        __syncthreads();
    }
}

// ---------------- phase 2: per-edge gather + activations ---------------------
// 2 edges/thread (split halves). Per edge: two aligned u32 loads cover the
// 3 contiguous fp16 scores; branchless parity select.
__global__ __launch_bounds__(256) void zinb_gather(
    const int* __restrict__ src, const int* __restrict__ dst,
    const float* __restrict__ cs_factor, const float* __restrict__ gs_factor,
    const float* __restrict__ bm, const float* __restrict__ bd,
    const float* __restrict__ bp,
    float* __restrict__ out, int E)
{
    const int half = (E + 1) >> 1;
    const int t = blockIdx.x * blockDim.x + threadIdx.x;
    if (t >= half) return;
    const int e0 = t;
    const int e1 = t + half;
    const bool v1 = (e1 < E);

    const int s0 = __ldcs(src + e0);
    const int d0 = __ldcs(dst + e0);
    const int s1 = v1 ? __ldcs(src + e1) : 0;
    const int d1 = v1 ? __ldcs(dst + e1) : 0;

    const uint64_t pol = mk_pol_evict_last();
    const uint32_t* cw = (const uint32_t*)g_Ch;

    const size_t h0 = (size_t)s0 * N_PAD + 3 * (size_t)d0;
    const size_t h1 = (size_t)s1 * N_PAD + 3 * (size_t)d1;
    const size_t w0 = h0 >> 1, w1 = h1 >> 1;
    const bool o0 = (h0 & 1), o1 = (h1 & 1);

    const uint32_t a0 = ld_c32_el(cw + w0, pol);
    const uint32_t b0v = ld_c32_el(cw + w0 + 1, pol);
    const uint32_t a1 = ld_c32_el(cw + w1, pol);
    const uint32_t b1v = ld_c32_el(cw + w1 + 1, pol);

    const __half2 ha0 = *(const __half2*)&a0, hb0 = *(const __half2*)&b0v;
    const __half2 ha1 = *(const __half2*)&a1, hb1 = *(const __half2*)&b1v;

    const float sm0 = __half2float(o0 ? __high2half(ha0) : __low2half(ha0));
    const float sd0 = __half2float(o0 ? __low2half(hb0) : __high2half(ha0));
    const float sp0 = __half2float(o0 ? __high2half(hb0) : __low2half(hb0));
    const float sm1 = __half2float(o1 ? __high2half(ha1) : __low2half(ha1));
    const float sd1 = __half2float(o1 ? __low2half(hb1) : __high2half(ha1));
    const float sp1 = __half2float(o1 ? __high2half(hb1) : __low2half(hb1));

    const float gs0 = __ldg(gs_factor + d0);
    const float cs0 = __ldg(cs_factor + s0);
    const float gs1 = __ldg(gs_factor + d1);
    const float cs1 = __ldg(cs_factor + s1);
    const float bmv = __ldg(bm), bdv = __ldg(bd), bpv = __ldg(bp);

    {
        const float mu_ = 1.0f / (1.0f + __expf(-(sm0 + bmv)));
        const float piv = 1.0f / (1.0f + __expf(-(sp0 + bpv)));
        const float x = gs0 * (sd0 + bdv);
        const float spv = fmaxf(x, 0.0f) + log1pf(__expf(-fabsf(x)));
        const float dispv = fminf(fmaxf(spv, 1e-4f), 1e4f);
        const float muv = cs0 * fminf(fmaxf(__expf(gs0 * mu_) - 1.0f, 1e-5f), 1e6f);
        __stcs(out + e0, muv);
        __stcs(out + e0 + E, dispv);
        __stcs(out + e0 + 2 * (size_t)E, piv);
    }
    if (v1) {
        const float mu_ = 1.0f / (1.0f + __expf(-(sm1 + bmv)));
        const float piv = 1.0f / (1.0f + __expf(-(sp1 + bpv)));
        const float x = gs1 * (sd1 + bdv);
        const float spv = fmaxf(x, 0.0f) + log1pf(__expf(-fabsf(x)));
        const float dispv = fminf(fmaxf(spv, 1e-4f), 1e4f);
        const float muv = cs1 * fminf(fmaxf(__expf(gs1 * mu_) - 1.0f, 1e-5f), 1e6f);
        __stcs(out + e1, muv);
        __stcs(out + e1 + E, dispv);
        __stcs(out + e1 + 2 * (size_t)E, piv);
    }
}

// ---------------- launch -----------------------------------------------------
extern "C" void kernel_launch(void* const* d_in, const int* in_sizes, int n_in,
                              void* d_out, int out_size) {
    const float* c_feat    = (const float*)d_in[0];
    const float* g_feat    = (const float*)d_in[1];
    const float* cs_factor = (const float*)d_in[2];
    const float* gs_factor = (const float*)d_in[3];
    const int*   src       = (const int*)d_in[4];
    const int*   dst       = (const int*)d_in[5];
    const float* Wm        = (const float*)d_in[6];
    const float* bm        = (const float*)d_in[7];
    const float* Wd        = (const float*)d_in[8];
    const float* bd        = (const float*)d_in[9];
    const float* Wp        = (const float*)d_in[10];
    const float* bp        = (const float*)d_in[11];
    float* out = (float*)d_out;
    const int E = in_sizes[4];

    const int nPrep = (M_PAD + N_PAD) * DD;
    prep_AB<<<(nPrep + 255) / 256, 256>>>(c_feat, g_feat, Wm, Wd, Wp);

    const int dyn_bytes = 3 * 128 * SA;   // 55296
    cudaFuncSetAttribute(zinb_gemm, cudaFuncAttributeMaxDynamicSharedMemorySize,
                         dyn_bytes);
    dim3 grid(NTT, NGRP);
    zinb_gemm<<<grid, 256, dyn_bytes>>>();

    const int half = (E + 1) >> 1;
    zinb_gather<<<(half + 255) / 256, 256>>>(src, dst, cs_factor, gs_factor,
                                             bm, bd, bp, out, E);
}